// round 3
// baseline (speedup 1.0000x reference)
#include <cuda_runtime.h>
#include <cstdint>

#define ALPHA 0.8f
#define SNB   16
#define IND   128
#define DOUT  64
#define EDIM  32
#define OUTW  (2*DOUT + EDIM)   // 160
#define MAXN  50176

// ---- device scratch (allocation-free rule: static __device__ globals) ----
__device__ __align__(16) float g_u[IND];
__device__ __align__(16) float g_v[IND];
__device__ __align__(16) float g_agg[(size_t)MAXN * IND];

// ---------------------------------------------------------------------------
// Kernel 1: u = W @ a_x, v = W2 @ a_n   (128x64 GEMVs, trivial)
// ---------------------------------------------------------------------------
__global__ void prep_kernel(const float* __restrict__ W,
                            const float* __restrict__ W2,
                            const float* __restrict__ a) {
    int k = threadIdx.x;   // 0..127
    float su = 0.f, sv = 0.f;
#pragma unroll
    for (int j = 0; j < DOUT; j++) {
        su += W [k * DOUT + j] * a[j];
        sv += W2[k * DOUT + j] * a[DOUT + j];
    }
    g_u[k] = su;
    g_v[k] = sv;
}

// ---------------------------------------------------------------------------
// Kernel 2: attention + aggregation (streaming, warp per node)
//   scores[n,s] = input[n]@u + neigh[n,s]@v + ee[n,s]@a_e  -> leaky -> softmax
//   g_agg[n]    = sum_s att * neigh[n,s]      (128-dim, pre-projection)
//   out[n,128+j]= sum_s att * ee[n,s][j]      (h_edge)
// ---------------------------------------------------------------------------
__global__ __launch_bounds__(128) void attn_kernel(
    const float* __restrict__ input, const float* __restrict__ neigh,
    const float* __restrict__ ee,    const float* __restrict__ a,
    float* __restrict__ out, int N) {

    __shared__ __align__(16) float s_u[IND];
    __shared__ __align__(16) float s_v[IND];
    __shared__ __align__(16) float s_ae[EDIM];

    int tid = threadIdx.x;
    if (tid < IND) { s_u[tid] = g_u[tid]; s_v[tid] = g_v[tid]; }
    if (tid < EDIM) s_ae[tid] = a[2 * DOUT + tid];
    __syncthreads();

    int lane = tid & 31;
    int n = blockIdx.x * 4 + (tid >> 5);
    if (n >= N) return;

    float4 in4 = ((const float4*)(input + (size_t)n * IND))[lane];
    float4 u4  = ((const float4*)s_u)[lane];
    float4 v4  = ((const float4*)s_v)[lane];
    float  ae  = s_ae[lane];

    const float4* nrow = (const float4*)(neigh + (size_t)n * SNB * IND);
    const float*  erow = ee + (size_t)n * SNB * EDIM;

    // Batch all streaming loads up front (MLP = 33 per warp)
    float4 nb[SNB];
    float  ev[SNB];
#pragma unroll
    for (int s = 0; s < SNB; s++) {
        nb[s] = nrow[s * 32 + lane];       // 512B coalesced per row
        ev[s] = erow[s * EDIM + lane];     // 128B coalesced per row
    }

    // s_x = input[n] @ u
    float sx = in4.x*u4.x + in4.y*u4.y + in4.z*u4.z + in4.w*u4.w;
#pragma unroll
    for (int o = 16; o; o >>= 1) sx += __shfl_xor_sync(0xffffffffu, sx, o);

    // per-neighbor scores
    float sc[SNB];
#pragma unroll
    for (int s = 0; s < SNB; s++) {
        float p = nb[s].x*v4.x + nb[s].y*v4.y + nb[s].z*v4.z + nb[s].w*v4.w
                + ev[s] * ae;
#pragma unroll
        for (int o = 16; o; o >>= 1) p += __shfl_xor_sync(0xffffffffu, p, o);
        float t = sx + p;
        sc[s] = t > 0.f ? t : ALPHA * t;   // leaky relu
    }

    // softmax over S=16 (all lanes hold identical sc[])
    float mx = sc[0];
#pragma unroll
    for (int s = 1; s < SNB; s++) mx = fmaxf(mx, sc[s]);
    float sum = 0.f;
#pragma unroll
    for (int s = 0; s < SNB; s++) { sc[s] = __expf(sc[s] - mx); sum += sc[s]; }
    float inv = 1.0f / sum;

    // weighted aggregation in the 128-dim input space + edge space
    float4 ag = make_float4(0.f, 0.f, 0.f, 0.f);
    float  he = 0.f;
#pragma unroll
    for (int s = 0; s < SNB; s++) {
        float w = sc[s] * inv;
        ag.x += w * nb[s].x; ag.y += w * nb[s].y;
        ag.z += w * nb[s].z; ag.w += w * nb[s].w;
        he   += w * ev[s];
    }

    ((float4*)(g_agg + (size_t)n * IND))[lane] = ag;
    out[(size_t)n * OUTW + 2 * DOUT + lane] = he;
}

// ---------------------------------------------------------------------------
// Kernel 3: two skinny GEMMs (50000x128 @ 128x64) with tf32 MMA, hi/lo split
//   blockIdx.y == 0 : out[:, 0:64]   = input @ W
//   blockIdx.y == 1 : out[:, 64:128] = g_agg @ W2
// ---------------------------------------------------------------------------
__device__ __forceinline__ uint32_t f2tf(float f) {
    uint32_t r;
    asm("cvt.rna.tf32.f32 %0, %1;" : "=r"(r) : "f"(f));
    return r;
}

__device__ __forceinline__ void mma_tf32(float c[4], const uint32_t a[4],
                                         uint32_t b0, uint32_t b1) {
    asm volatile(
        "mma.sync.aligned.m16n8k8.row.col.f32.tf32.tf32.f32 "
        "{%0,%1,%2,%3}, {%4,%5,%6,%7}, {%8,%9}, {%0,%1,%2,%3};"
        : "+f"(c[0]), "+f"(c[1]), "+f"(c[2]), "+f"(c[3])
        : "r"(a[0]), "r"(a[1]), "r"(a[2]), "r"(a[3]), "r"(b0), "r"(b1));
}

__global__ __launch_bounds__(128) void gemm_kernel(
    const float* __restrict__ input, const float* __restrict__ W,
    const float* __restrict__ W2, float* __restrict__ out, int N) {

    __shared__ float Bs[IND][72];   // stride 72 words -> conflict-free B frags

    int sel = blockIdx.y;
    const float* A = sel ? g_agg : input;
    const float* B = sel ? W2 : W;
    int tid = threadIdx.x;

    // stage W (128x64 fp32) into shared
    for (int i = tid; i < IND * DOUT / 4; i += 128) {
        float4 b4 = ((const float4*)B)[i];
        int k = (i * 4) / DOUT, nn = (i * 4) % DOUT;
        Bs[k][nn]     = b4.x; Bs[k][nn + 1] = b4.y;
        Bs[k][nn + 2] = b4.z; Bs[k][nn + 3] = b4.w;
    }
    __syncthreads();

    int warp = tid >> 5, lane = tid & 31;
    int g = lane >> 2, t = lane & 3;
    int rowbase = blockIdx.x * 64 + warp * 16;
    int r0 = rowbase + g, r1 = r0 + 8;
    bool v0 = (r0 < N), v1 = (r1 < N);

    // batch all A-fragment loads (64 scalars/lane, deep MLP, each elem read once)
    float araw[64];
#pragma unroll
    for (int kc = 0; kc < 16; kc++) {
        int c0 = kc * 8 + t;
        araw[kc*4+0] = v0 ? A[(size_t)r0 * IND + c0]     : 0.f;
        araw[kc*4+1] = v1 ? A[(size_t)r1 * IND + c0]     : 0.f;
        araw[kc*4+2] = v0 ? A[(size_t)r0 * IND + c0 + 4] : 0.f;
        araw[kc*4+3] = v1 ? A[(size_t)r1 * IND + c0 + 4] : 0.f;
    }

    float c[8][4];
#pragma unroll
    for (int nt = 0; nt < 8; nt++)
#pragma unroll
        for (int i = 0; i < 4; i++) c[nt][i] = 0.f;

#pragma unroll
    for (int kc = 0; kc < 16; kc++) {
        uint32_t ah[4], al[4];
#pragma unroll
        for (int i = 0; i < 4; i++) {
            float av = araw[kc*4 + i];
            uint32_t h = f2tf(av);
            ah[i] = h;
            al[i] = f2tf(av - __uint_as_float(h));
        }
        int k0 = kc * 8 + t;
#pragma unroll
        for (int nt = 0; nt < 8; nt++) {
            int col = nt * 8 + g;
            float b0f = Bs[k0][col];
            float b1f = Bs[k0 + 4][col];
            uint32_t bh0 = f2tf(b0f);
            uint32_t bl0 = f2tf(b0f - __uint_as_float(bh0));
            uint32_t bh1 = f2tf(b1f);
            uint32_t bl1 = f2tf(b1f - __uint_as_float(bh1));
            // D = Ah*Bh + Al*Bh + Ah*Bl  (error ~ Al*Bl ~ 2^-22, fp32-grade)
            mma_tf32(c[nt], ah, bh0, bh1);
            mma_tf32(c[nt], al, bh0, bh1);
            mma_tf32(c[nt], ah, bl0, bl1);
        }
    }

    int cb = sel * DOUT;
#pragma unroll
    for (int nt = 0; nt < 8; nt++) {
        int col = cb + nt * 8 + 2 * t;
        if (v0) *(float2*)(out + (size_t)r0 * OUTW + col) = make_float2(c[nt][0], c[nt][1]);
        if (v1) *(float2*)(out + (size_t)r1 * OUTW + col) = make_float2(c[nt][2], c[nt][3]);
    }
}

// ---------------------------------------------------------------------------
extern "C" void kernel_launch(void* const* d_in, const int* in_sizes, int n_in,
                              void* d_out, int out_size) {
    const float* input = (const float*)d_in[0];   // (N, 128)
    const float* neigh = (const float*)d_in[1];   // (N*16, 128)
    const float* ee    = (const float*)d_in[2];   // (N*16, 32)
    const float* W     = (const float*)d_in[3];   // (128, 64)
    const float* W2    = (const float*)d_in[4];   // (128, 64)
    const float* a     = (const float*)d_in[5];   // (160, 1)
    float* out = (float*)d_out;                   // (N, 160)
    int N = in_sizes[0] / IND;

    prep_kernel<<<1, 128>>>(W, W2, a);
    attn_kernel<<<(N + 3) / 4, 128>>>(input, neigh, ee, a, out, N);
    dim3 ggrid((N + 63) / 64, 2);
    gemm_kernel<<<ggrid, 128>>>(input, W, W2, out, N);
}

// round 5
// speedup vs baseline: 1.0216x; 1.0216x over previous
#include <cuda_runtime.h>
#include <cstdint>

#define ALPHA 0.8f
#define SNB   16
#define IND   128
#define DOUT  64
#define EDIM  32
#define OUTW  (2*DOUT + EDIM)   // 160
#define MAXN  50176

// ---- device scratch (allocation-free rule: static __device__ globals) ----
__device__ __align__(16) float g_u[IND];
__device__ __align__(16) float g_v[IND];
__device__ __align__(16) float g_agg[(size_t)MAXN * IND];

// ---------------------------------------------------------------------------
// Kernel 1: u = W @ a_x, v = W2 @ a_n
// 512 threads: thread = (k, q); q in 0..3 handles 16 contiguous j's via float4.
// Warp loads are fully coalesced (2KB contiguous per warp per step).
// ---------------------------------------------------------------------------
__global__ __launch_bounds__(512) void prep_kernel(const float* __restrict__ W,
                                                   const float* __restrict__ W2,
                                                   const float* __restrict__ a) {
    int tid = threadIdx.x;
    int k = tid >> 2;          // 0..127
    int q = tid & 3;           // 0..3
    const float4* W4  = (const float4*)W;
    const float4* W24 = (const float4*)W2;
    const float4* ax4 = (const float4*)a;          // a[0:64]
    const float4* an4 = (const float4*)(a + DOUT); // a[64:128]

    float su = 0.f, sv = 0.f;
    int base = (k * DOUT + q * 16) >> 2;   // float4 index
    int abase = (q * 16) >> 2;
#pragma unroll
    for (int jj = 0; jj < 4; jj++) {
        float4 w4 = W4[base + jj];
        float4 x4 = ax4[abase + jj];
        su += w4.x*x4.x + w4.y*x4.y + w4.z*x4.z + w4.w*x4.w;
        float4 v4 = W24[base + jj];
        float4 n4 = an4[abase + jj];
        sv += v4.x*n4.x + v4.y*n4.y + v4.z*n4.z + v4.w*n4.w;
    }
    // reduce across the quad (lanes k*4..k*4+3 are in the same warp)
    su += __shfl_xor_sync(0xffffffffu, su, 1);
    su += __shfl_xor_sync(0xffffffffu, su, 2);
    sv += __shfl_xor_sync(0xffffffffu, sv, 1);
    sv += __shfl_xor_sync(0xffffffffu, sv, 2);
    if (q == 0) { g_u[k] = su; g_v[k] = sv; }
}

// ---------------------------------------------------------------------------
// Kernel 2: attention + aggregation, single pass, chunked (2 x 8 neighbors).
// Softmax computed WITHOUT max subtraction (scores bounded ~ +-8; exp safe in
// fp32; mathematically identical). Accumulate unnormalized, normalize once.
// ---------------------------------------------------------------------------
__global__ __launch_bounds__(256) void attn_kernel(
    const float* __restrict__ input, const float* __restrict__ neigh,
    const float* __restrict__ ee,    const float* __restrict__ a,
    float* __restrict__ out, int N) {

    __shared__ __align__(16) float s_u[IND];
    __shared__ __align__(16) float s_v[IND];
    __shared__ __align__(16) float s_ae[EDIM];

    int tid = threadIdx.x;
    if (tid < IND) { s_u[tid] = g_u[tid]; s_v[tid] = g_v[tid]; }
    else if (tid >= IND && tid < IND + EDIM) s_ae[tid - IND] = a[2 * DOUT + (tid - IND)];
    __syncthreads();

    int lane = tid & 31;
    int n = blockIdx.x * 8 + (tid >> 5);
    if (n >= N) return;

    float4 in4 = ((const float4*)(input + (size_t)n * IND))[lane];
    float4 u4  = ((const float4*)s_u)[lane];
    float4 v4  = ((const float4*)s_v)[lane];
    float  ae  = s_ae[lane];

    const float4* nrow = (const float4*)(neigh + (size_t)n * SNB * IND);
    const float*  erow = ee + (size_t)n * SNB * EDIM;

    // s_x = input[n] @ u  (broadcast to all lanes)
    float sx = in4.x*u4.x + in4.y*u4.y + in4.z*u4.z + in4.w*u4.w;
#pragma unroll
    for (int o = 16; o; o >>= 1) sx += __shfl_xor_sync(0xffffffffu, sx, o);

    float4 ag = make_float4(0.f, 0.f, 0.f, 0.f);
    float  he = 0.f, ssum = 0.f;

#pragma unroll
    for (int c = 0; c < 2; c++) {
        // batch-load 8 neighbor rows + 8 edge rows (MLP ~17/warp)
        float4 nb[8];
        float  ev[8];
#pragma unroll
        for (int s = 0; s < 8; s++) {
            int sg = c * 8 + s;
            nb[s] = nrow[sg * 32 + lane];        // 512B coalesced
            ev[s] = erow[sg * EDIM + lane];      // 128B coalesced
        }
        // partial scores
        float p[8];
#pragma unroll
        for (int s = 0; s < 8; s++)
            p[s] = nb[s].x*v4.x + nb[s].y*v4.y + nb[s].z*v4.z + nb[s].w*v4.w
                 + ev[s] * ae;
        // 8 independent butterfly reductions, stage-major (no serial chains)
#pragma unroll
        for (int o = 16; o; o >>= 1)
#pragma unroll
            for (int s = 0; s < 8; s++)
                p[s] += __shfl_xor_sync(0xffffffffu, p[s], o);
        // leaky-relu -> exp -> unnormalized accumulate
#pragma unroll
        for (int s = 0; s < 8; s++) {
            float t = sx + p[s];
            t = t > 0.f ? t : ALPHA * t;
            float e = __expf(t);
            ssum += e;
            ag.x += e * nb[s].x; ag.y += e * nb[s].y;
            ag.z += e * nb[s].z; ag.w += e * nb[s].w;
            he   += e * ev[s];
        }
    }

    float inv = 1.0f / ssum;
    ag.x *= inv; ag.y *= inv; ag.z *= inv; ag.w *= inv;
    he *= inv;

    ((float4*)(g_agg + (size_t)n * IND))[lane] = ag;
    out[(size_t)n * OUTW + 2 * DOUT + lane] = he;
}

// ---------------------------------------------------------------------------
// Kernel 3: two skinny GEMMs (N x 128 @ 128 x 64), tf32 MMA with hi/lo split
//   blockIdx.y == 0 : out[:, 0:64]   = input @ W
//   blockIdx.y == 1 : out[:, 64:128] = g_agg @ W2
// ---------------------------------------------------------------------------
__device__ __forceinline__ uint32_t f2tf(float f) {
    uint32_t r;
    asm("cvt.rna.tf32.f32 %0, %1;" : "=r"(r) : "f"(f));
    return r;
}

__device__ __forceinline__ void mma_tf32(float c[4], const uint32_t a[4],
                                         uint32_t b0, uint32_t b1) {
    asm volatile(
        "mma.sync.aligned.m16n8k8.row.col.f32.tf32.tf32.f32 "
        "{%0,%1,%2,%3}, {%4,%5,%6,%7}, {%8,%9}, {%0,%1,%2,%3};"
        : "+f"(c[0]), "+f"(c[1]), "+f"(c[2]), "+f"(c[3])
        : "r"(a[0]), "r"(a[1]), "r"(a[2]), "r"(a[3]), "r"(b0), "r"(b1));
}

__global__ __launch_bounds__(128) void gemm_kernel(
    const float* __restrict__ input, const float* __restrict__ W,
    const float* __restrict__ W2, float* __restrict__ out, int N) {

    __shared__ float Bs[IND][72];   // stride 72 words -> conflict-free B frags

    int sel = blockIdx.y;
    const float* A = sel ? g_agg : input;
    const float* B = sel ? W2 : W;
    int tid = threadIdx.x;

    for (int i = tid; i < IND * DOUT / 4; i += 128) {
        float4 b4 = ((const float4*)B)[i];
        int k = (i * 4) / DOUT, nn = (i * 4) % DOUT;
        Bs[k][nn]     = b4.x; Bs[k][nn + 1] = b4.y;
        Bs[k][nn + 2] = b4.z; Bs[k][nn + 3] = b4.w;
    }
    __syncthreads();

    int warp = tid >> 5, lane = tid & 31;
    int g = lane >> 2, t = lane & 3;
    int rowbase = blockIdx.x * 64 + warp * 16;
    int r0 = rowbase + g, r1 = r0 + 8;
    bool v0 = (r0 < N), v1 = (r1 < N);

    float araw[64];
#pragma unroll
    for (int kc = 0; kc < 16; kc++) {
        int c0 = kc * 8 + t;
        araw[kc*4+0] = v0 ? A[(size_t)r0 * IND + c0]     : 0.f;
        araw[kc*4+1] = v1 ? A[(size_t)r1 * IND + c0]     : 0.f;
        araw[kc*4+2] = v0 ? A[(size_t)r0 * IND + c0 + 4] : 0.f;
        araw[kc*4+3] = v1 ? A[(size_t)r1 * IND + c0 + 4] : 0.f;
    }

    float c[8][4];
#pragma unroll
    for (int nt = 0; nt < 8; nt++)
#pragma unroll
        for (int i = 0; i < 4; i++) c[nt][i] = 0.f;

#pragma unroll
    for (int kc = 0; kc < 16; kc++) {
        uint32_t ah[4], al[4];
#pragma unroll
        for (int i = 0; i < 4; i++) {
            float av = araw[kc*4 + i];
            uint32_t h = f2tf(av);
            ah[i] = h;
            al[i] = f2tf(av - __uint_as_float(h));
        }
        int k0 = kc * 8 + t;
#pragma unroll
        for (int nt = 0; nt < 8; nt++) {
            int col = nt * 8 + g;
            float b0f = Bs[k0][col];
            float b1f = Bs[k0 + 4][col];
            uint32_t bh0 = f2tf(b0f);
            uint32_t bl0 = f2tf(b0f - __uint_as_float(bh0));
            uint32_t bh1 = f2tf(b1f);
            uint32_t bl1 = f2tf(b1f - __uint_as_float(bh1));
            mma_tf32(c[nt], ah, bh0, bh1);
            mma_tf32(c[nt], al, bh0, bh1);
            mma_tf32(c[nt], ah, bl0, bl1);
        }
    }

    int cb = sel * DOUT;
#pragma unroll
    for (int nt = 0; nt < 8; nt++) {
        int col = cb + nt * 8 + 2 * t;
        if (v0) *(float2*)(out + (size_t)r0 * OUTW + col) = make_float2(c[nt][0], c[nt][1]);
        if (v1) *(float2*)(out + (size_t)r1 * OUTW + col) = make_float2(c[nt][2], c[nt][3]);
    }
}

// ---------------------------------------------------------------------------
extern "C" void kernel_launch(void* const* d_in, const int* in_sizes, int n_in,
                              void* d_out, int out_size) {
    const float* input = (const float*)d_in[0];   // (N, 128)
    const float* neigh = (const float*)d_in[1];   // (N*16, 128)
    const float* ee    = (const float*)d_in[2];   // (N*16, 32)
    const float* W     = (const float*)d_in[3];   // (128, 64)
    const float* W2    = (const float*)d_in[4];   // (128, 64)
    const float* a     = (const float*)d_in[5];   // (160, 1)
    float* out = (float*)d_out;                   // (N, 160)
    int N = in_sizes[0] / IND;

    prep_kernel<<<1, 512>>>(W, W2, a);
    attn_kernel<<<(N + 7) / 8, 256>>>(input, neigh, ee, a, out, N);
    dim3 ggrid((N + 63) / 64, 2);
    gemm_kernel<<<ggrid, 128>>>(input, W, W2, out, N);
}

// round 6
// speedup vs baseline: 1.1757x; 1.1508x over previous
#include <cuda_runtime.h>
#include <cstdint>

#define ALPHA 0.8f
#define SNB   16
#define IND   128
#define DOUT  64
#define EDIM  32
#define OUTW  (2*DOUT + EDIM)   // 160

// ---- device scratch (allocation-free rule: static __device__ globals) ----
__device__ __align__(16) float g_u[IND];
__device__ __align__(16) float g_v[IND];
// Pre-split tf32 B fragments, MMA-frag-layout packed:
//   entry e = ((m*16 + kc)*8 + w)*32 + lane,  value = (bh0, bh1, bl0, bl1)
//   b0 = B_m[(kc*8+t)*64 + w*8+g],  b1 = B_m[(kc*8+4+t)*64 + w*8+g]
__device__ __align__(16) uint4 g_bfrag[2 * 16 * 8 * 32];

__device__ __forceinline__ uint32_t f2tf(float f) {
    uint32_t r;
    asm("cvt.rna.tf32.f32 %0, %1;" : "=r"(r) : "f"(f));
    return r;
}

__device__ __forceinline__ void mma_tf32(float c[4], const uint32_t a[4],
                                         uint32_t b0, uint32_t b1) {
    asm volatile(
        "mma.sync.aligned.m16n8k8.row.col.f32.tf32.tf32.f32 "
        "{%0,%1,%2,%3}, {%4,%5,%6,%7}, {%8,%9}, {%0,%1,%2,%3};"
        : "+f"(c[0]), "+f"(c[1]), "+f"(c[2]), "+f"(c[3])
        : "r"(a[0]), "r"(a[1]), "r"(a[2]), "r"(a[3]), "r"(b0), "r"(b1));
}

// ---------------------------------------------------------------------------
// Kernel 1 (prep): blocks 0..15 pack B fragments, block 16 computes u, v.
// ---------------------------------------------------------------------------
__global__ __launch_bounds__(512) void prep_kernel(const float* __restrict__ W,
                                                   const float* __restrict__ W2,
                                                   const float* __restrict__ a) {
    int tid = threadIdx.x;
    if (blockIdx.x < 16) {
        // ---- pack pre-split tf32 B fragments (8192 entries total) ----
        int e    = blockIdx.x * 512 + tid;
        int lane = e & 31;
        int w    = (e >> 5) & 7;
        int kc   = (e >> 8) & 15;
        int m    = e >> 12;
        int g = lane >> 2, t = lane & 3;
        const float* B = m ? W2 : W;
        float b0 = B[(kc * 8 + t) * DOUT + w * 8 + g];
        float b1 = B[(kc * 8 + 4 + t) * DOUT + w * 8 + g];
        uint32_t h0 = f2tf(b0), h1 = f2tf(b1);
        uint32_t l0 = f2tf(b0 - __uint_as_float(h0));
        uint32_t l1 = f2tf(b1 - __uint_as_float(h1));
        g_bfrag[e] = make_uint4(h0, h1, l0, l1);
    } else {
        // ---- u = W @ a_x, v = W2 @ a_n ----
        int k = tid >> 2;          // 0..127
        int q = tid & 3;           // 0..3
        const float4* W4  = (const float4*)W;
        const float4* W24 = (const float4*)W2;
        const float4* ax4 = (const float4*)a;
        const float4* an4 = (const float4*)(a + DOUT);
        float su = 0.f, sv = 0.f;
        int base  = (k * DOUT + q * 16) >> 2;
        int abase = (q * 16) >> 2;
#pragma unroll
        for (int jj = 0; jj < 4; jj++) {
            float4 w4 = W4[base + jj],  x4 = ax4[abase + jj];
            su += w4.x*x4.x + w4.y*x4.y + w4.z*x4.z + w4.w*x4.w;
            float4 v4 = W24[base + jj], n4 = an4[abase + jj];
            sv += v4.x*n4.x + v4.y*n4.y + v4.z*n4.z + v4.w*n4.w;
        }
        su += __shfl_xor_sync(0xffffffffu, su, 1);
        su += __shfl_xor_sync(0xffffffffu, su, 2);
        sv += __shfl_xor_sync(0xffffffffu, sv, 1);
        sv += __shfl_xor_sync(0xffffffffu, sv, 2);
        if (q == 0) { g_u[k] = su; g_v[k] = sv; }
    }
}

// ---------------------------------------------------------------------------
// Kernel 2 (fused): attention + aggregation + BOTH output projections.
// Phase 1: warp-per-node streaming (scores, softmax, 128-dim aggregate,
//          h_edge written directly). Input row + aggregate row deposited in a
//          16x128 shared A-tile (rows 0-7 input, rows 8-15 agg).
// Phase 2: warp w computes 8-column n-tile w of x@W (rows 0-7) and agg@W2
//          (rows 8-15) via tf32 hi/lo MMA. No g_agg scratch, no second kernel.
// ---------------------------------------------------------------------------
__global__ __launch_bounds__(256) void fused_kernel(
    const float* __restrict__ input, const float* __restrict__ neigh,
    const float* __restrict__ ee,    const float* __restrict__ a,
    float* __restrict__ out, int N) {

    __shared__ __align__(16) float s_u[IND];
    __shared__ __align__(16) float s_v[IND];
    __shared__ __align__(16) float s_ae[EDIM];
    __shared__ __align__(16) float sA[16][132];   // stride 132: conflict-free frags

    int tid  = threadIdx.x;
    int lane = tid & 31;
    int wid  = tid >> 5;          // warp id 0..7 == node slot == n-tile id

    if (tid < IND) { s_u[tid] = g_u[tid]; s_v[tid] = g_v[tid]; }
    else if (tid < IND + EDIM) s_ae[tid - IND] = a[2 * DOUT + (tid - IND)];

    int n = blockIdx.x * 8 + wid;
    bool valid = (n < N);

    float4 in4 = make_float4(0.f, 0.f, 0.f, 0.f);
    if (valid) in4 = ((const float4*)(input + (size_t)n * IND))[lane];
    *(float4*)&sA[wid][lane * 4] = in4;           // A rows 0-7: input

    __syncthreads();                               // s_u/s_v/s_ae ready

    float4 u4 = ((const float4*)s_u)[lane];
    float4 v4 = ((const float4*)s_v)[lane];
    float  ae = s_ae[lane];

    float4 ag = make_float4(0.f, 0.f, 0.f, 0.f);
    float  he = 0.f;

    if (valid) {
        const float4* nrow = (const float4*)(neigh + (size_t)n * SNB * IND);
        const float*  erow = ee + (size_t)n * SNB * EDIM;

        // s_x = input[n] @ u (broadcast)
        float sx = in4.x*u4.x + in4.y*u4.y + in4.z*u4.z + in4.w*u4.w;
#pragma unroll
        for (int o = 16; o; o >>= 1) sx += __shfl_xor_sync(0xffffffffu, sx, o);

        float ssum = 0.f;
#pragma unroll
        for (int c = 0; c < 2; c++) {
            float4 nb[8];
            float  ev[8];
#pragma unroll
            for (int s = 0; s < 8; s++) {
                int sg = c * 8 + s;
                nb[s] = nrow[sg * 32 + lane];
                ev[s] = erow[sg * EDIM + lane];
            }
            float p[8];
#pragma unroll
            for (int s = 0; s < 8; s++)
                p[s] = nb[s].x*v4.x + nb[s].y*v4.y + nb[s].z*v4.z + nb[s].w*v4.w
                     + ev[s] * ae;
#pragma unroll
            for (int o = 16; o; o >>= 1)
#pragma unroll
                for (int s = 0; s < 8; s++)
                    p[s] += __shfl_xor_sync(0xffffffffu, p[s], o);
#pragma unroll
            for (int s = 0; s < 8; s++) {
                float t = sx + p[s];
                t = t > 0.f ? t : ALPHA * t;        // leaky relu
                float e = __expf(t);                 // no-max softmax (bounded)
                ssum += e;
                ag.x += e * nb[s].x; ag.y += e * nb[s].y;
                ag.z += e * nb[s].z; ag.w += e * nb[s].w;
                he   += e * ev[s];
            }
        }
        float inv = 1.0f / ssum;
        ag.x *= inv; ag.y *= inv; ag.z *= inv; ag.w *= inv;
        he *= inv;
        out[(size_t)n * OUTW + 2 * DOUT + lane] = he;
    }
    *(float4*)&sA[8 + wid][lane * 4] = ag;        // A rows 8-15: aggregate

    __syncthreads();                               // A tile complete

    // ---- Phase 2: tf32 MMA, n-tile = wid, both matrices ----
    int g = lane >> 2, t = lane & 3;
    float c0[4] = {0.f, 0.f, 0.f, 0.f};           // x @ W   (keep rows 0-7)
    float c1[4] = {0.f, 0.f, 0.f, 0.f};           // agg @ W2 (keep rows 8-15)

#pragma unroll
    for (int kc = 0; kc < 16; kc++) {
        int k0 = kc * 8 + t;
        float a0 = sA[g][k0],     a1 = sA[g + 8][k0];
        float a2 = sA[g][k0 + 4], a3 = sA[g + 8][k0 + 4];
        uint32_t ah[4], al[4];
        ah[0] = f2tf(a0); al[0] = f2tf(a0 - __uint_as_float(ah[0]));
        ah[1] = f2tf(a1); al[1] = f2tf(a1 - __uint_as_float(ah[1]));
        ah[2] = f2tf(a2); al[2] = f2tf(a2 - __uint_as_float(ah[2]));
        ah[3] = f2tf(a3); al[3] = f2tf(a3 - __uint_as_float(ah[3]));

        uint4 b0 = g_bfrag[(kc * 8 + wid) * 32 + lane];            // W
        uint4 b1 = g_bfrag[4096 + (kc * 8 + wid) * 32 + lane];     // W2

        mma_tf32(c0, ah, b0.x, b0.y);
        mma_tf32(c0, al, b0.x, b0.y);
        mma_tf32(c0, ah, b0.z, b0.w);

        mma_tf32(c1, ah, b1.x, b1.y);
        mma_tf32(c1, al, b1.x, b1.y);
        mma_tf32(c1, ah, b1.z, b1.w);
    }

    int n0 = blockIdx.x * 8 + g;                   // node for A-row g (and g+8)
    if (n0 < N) {
        // x@W -> cols [0,64): D rows 0-7 => c0[0], c0[1]
        *(float2*)(out + (size_t)n0 * OUTW + wid * 8 + 2 * t) =
            make_float2(c0[0], c0[1]);
        // agg@W2 -> cols [64,128): D rows 8-15 => c1[2], c1[3]
        *(float2*)(out + (size_t)n0 * OUTW + DOUT + wid * 8 + 2 * t) =
            make_float2(c1[2], c1[3]);
    }
}

// ---------------------------------------------------------------------------
extern "C" void kernel_launch(void* const* d_in, const int* in_sizes, int n_in,
                              void* d_out, int out_size) {
    const float* input = (const float*)d_in[0];   // (N, 128)
    const float* neigh = (const float*)d_in[1];   // (N*16, 128)
    const float* ee    = (const float*)d_in[2];   // (N*16, 32)
    const float* W     = (const float*)d_in[3];   // (128, 64)
    const float* W2    = (const float*)d_in[4];   // (128, 64)
    const float* a     = (const float*)d_in[5];   // (160, 1)
    float* out = (float*)d_out;                   // (N, 160)
    int N = in_sizes[0] / IND;

    prep_kernel<<<17, 512>>>(W, W2, a);
    fused_kernel<<<(N + 7) / 8, 256>>>(input, neigh, ee, a, out, N);
}